// round 16
// baseline (speedup 1.0000x reference)
#include <cuda_runtime.h>

// Problem constants (fixed shapes from reference: x[32,3,512,512] fp32)
#define NB        32
#define HW        262144            // 512*512
#define NBINS     256
#define F4_PER_B  (HW / 4)          // 65536 float4 groups per channel plane
#define BLK_PER_B 32
#define TOTAL_BLK (BLK_PER_B * NB)  // 1024
#define THREADS   256
#define NWARP     (THREADS / 32)    // 8
#define SUBW      257               // padded sub-hist width (bank rotation)
#define NUM_PIXEL 262400.0f         // H*W + 256

// Scratch (no allocation). Self-cleaning: the last-arriving block zeros
// g_hist while reading it and resets g_done, so every graph replay starts
// clean (first launch: BSS zero; replays: stream-ordered cleanup).
__device__ int g_hist[NB][NBINS];
__device__ unsigned int g_done;

// Release-arrive: orders this thread's prior (L2-atomic) writes before the
// increment, WITHOUT a full membar.gpu drain. Returns old value.
__device__ __forceinline__ unsigned int arrive_release(unsigned int* p) {
    unsigned int old;
    asm volatile("atom.add.release.gpu.u32 %0, [%1], 1;"
                 : "=r"(old) : "l"(p) : "memory");
    return old;
}
// Acquire: orders subsequent loads after this read.
__device__ __forceinline__ unsigned int load_acquire(unsigned int* p) {
    unsigned int v;
    asm volatile("ld.acquire.gpu.u32 %0, [%1];" : "=r"(v) : "l"(p) : "memory");
    return v;
}

__global__ void __launch_bounds__(THREADS)
fused_kernel(const float* __restrict__ x, float* __restrict__ out) {
    // Per-warp sub-histograms: no cross-warp same-address ATOMS contention.
    __shared__ int sh[NWARP * SUBW];
    __shared__ int s_last;
    const int b = blockIdx.y;
    const int t = threadIdx.x;
    const int w = t >> 5;

    for (int i = t; i < NWARP * SUBW; i += THREADS) sh[i] = 0;
    __syncthreads();

    // ---- Phase 1: histogram ----
    const float4* __restrict__ p0 = (const float4*)(x + (size_t)b * 3 * HW);
    const float4* __restrict__ p1 = p0 + F4_PER_B;
    const float4* __restrict__ p2 = p1 + F4_PER_B;

    int* __restrict__ msh = sh + w * SUBW;
    const float s = 255.0f / 3.0f;
    const int stride = BLK_PER_B * THREADS;       // 8192
    #pragma unroll
    for (int ch = 0; ch < 2; ch++) {
        const int base = blockIdx.x * THREADS + t + ch * 4 * stride;
        float4 v[4][3];
        #pragma unroll
        for (int u = 0; u < 4; u++) {
            int idx = base + u * stride;
            v[u][0] = p0[idx];
            v[u][1] = p1[idx];
            v[u][2] = p2[idx];
        }
        #pragma unroll
        for (int u = 0; u < 4; u++) {
            float4 a = v[u][0], c = v[u][1], d = v[u][2];
            int i0 = (int)((a.x + c.x + d.x) * s);
            int i1 = (int)((a.y + c.y + d.y) * s);
            int i2 = (int)((a.z + c.z + d.z) * s);
            int i3 = (int)((a.w + c.w + d.w) * s);
            i0 = min(max(i0, 0), 255);
            i1 = min(max(i1, 0), 255);
            i2 = min(max(i2, 0), 255);
            i3 = min(max(i3, 0), 255);
            atomicAdd(&msh[i0], 1);
            atomicAdd(&msh[i1], 1);
            atomicAdd(&msh[i2], 1);
            atomicAdd(&msh[i3], 1);
        }
    }
    __syncthreads();

    // Merge: thread t owns bin t; sum 8 warp copies, one global atomic.
    {
        int v = 0;
        #pragma unroll
        for (int ww = 0; ww < NWARP; ww++) v += sh[ww * SUBW + t];
        atomicAdd(&g_hist[b][t], v);
    }
    __syncthreads();

    // ---- Phase 2: release-arrive; only the last block continues ----
    if (t == 0)
        s_last = (arrive_release(&g_done) == TOTAL_BLK - 1);
    __syncthreads();
    if (!s_last) return;                 // 1023 of 1024 blocks retire here

    (void)load_acquire(&g_done);         // acquire all published merges

    // ---- Phase 3: entropy tail (deterministic fixed-order sums) ----
    __shared__ float warp_sum[NWARP];
    const float inv = 1.0f / NUM_PIXEL;
    float acc = 0.0f;

    #pragma unroll 8
    for (int bb = 0; bb < NB; bb++) {
        int raw = __ldcg(&g_hist[bb][t]);
        g_hist[bb][t] = 0;               // cleanup for next replay
        // bin-0 quirk: reference overwrites bin0 count with H*W.
        float cnt = (t == 0) ? (float)HW : (float)raw;
        float p = (cnt + 1.0f) * inv;    // '+1' smoothing
        acc += p * __logf(p);            // MUFU LG2; ~1e-6 rel err
    }

    #pragma unroll
    for (int m = 16; m > 0; m >>= 1)
        acc += __shfl_xor_sync(0xFFFFFFFF, acc, m);
    if ((t & 31) == 0) warp_sum[t >> 5] = acc;
    __syncthreads();
    if (t == 0) {
        float v = 0.0f;
        #pragma unroll
        for (int ww = 0; ww < NWARP; ww++) v += warp_sum[ww];
        out[0] = v / (float)NB;
        g_done = 0;                      // reset for next replay (plain store:
                                         // next launch is stream-ordered after)
    }
}

extern "C" void kernel_launch(void* const* d_in, const int* in_sizes, int n_in,
                              void* d_out, int out_size) {
    const float* x = (const float*)d_in[0];
    float* out = (float*)d_out;
    fused_kernel<<<dim3(BLK_PER_B, NB), THREADS>>>(x, out);
}

// round 17
// speedup vs baseline: 1.1786x; 1.1786x over previous
#include <cuda_runtime.h>

// Problem constants (fixed shapes from reference: x[32,3,512,512] fp32)
#define NB        32
#define HW        262144            // 512*512
#define NBINS     256
#define F4_PER_B  (HW / 4)          // 65536 float4 groups per channel plane
#define BLK_PER_B 32
#define THREADS   256
#define NUM_PIXEL 262400.0f         // H*W + 256

// Scratch (no allocation): per-batch integer histograms.
// Contract: zero at hist_kernel entry. First launch: BSS zero. Every replay:
// entropy_kernel zeroes each slot right after reading it (stream-ordered).
__device__ int g_hist[NB][NBINS];

__global__ void __launch_bounds__(THREADS)
hist_kernel(const float* __restrict__ x, float* __restrict__ out) {
    // Per-LANE column histogram: lane l always writes word (bin*32 + l),
    // whose smem bank is exactly l -> ATOMS bank-conflict-free by
    // construction. Cross-warp same-slot collisions need same (bin,lane)
    // in two warps at once (~1/256 per pair) -> negligible serialization.
    __shared__ int cnt[NBINS * 32];          // 32 KB
    const int b = blockIdx.y;
    const int t = threadIdx.x;
    const int lane = t & 31;

    // Zero the accumulator for this launch (sole writer; entropy_kernel runs
    // stream-after). d_out is poisoned pre-timing -> must init.
    if (blockIdx.x == 0 && b == 0 && t == 0) out[0] = 0.0f;

    #pragma unroll
    for (int i = t; i < NBINS * 32; i += THREADS) cnt[i] = 0;
    __syncthreads();

    // Channel planes for this batch: contiguous, HW floats apart.
    const float4* __restrict__ p0 = (const float4*)(x + (size_t)b * 3 * HW);
    const float4* __restrict__ p1 = p0 + F4_PER_B;
    const float4* __restrict__ p2 = p1 + F4_PER_B;

    const float s = 255.0f / 3.0f;
    const int stride = BLK_PER_B * THREADS;       // 8192
    // 8 positions per thread, 2 front-batched chunks of 4 (12 LDG.128 each).
    #pragma unroll
    for (int ch = 0; ch < 2; ch++) {
        const int base = blockIdx.x * THREADS + t + ch * 4 * stride;
        float4 v[4][3];
        #pragma unroll
        for (int u = 0; u < 4; u++) {
            int idx = base + u * stride;
            v[u][0] = p0[idx];
            v[u][1] = p1[idx];
            v[u][2] = p2[idx];
        }
        #pragma unroll
        for (int u = 0; u < 4; u++) {
            float4 a = v[u][0], c = v[u][1], d = v[u][2];
            int i0 = (int)((a.x + c.x + d.x) * s);
            int i1 = (int)((a.y + c.y + d.y) * s);
            int i2 = (int)((a.z + c.z + d.z) * s);
            int i3 = (int)((a.w + c.w + d.w) * s);
            i0 = min(max(i0, 0), 255);
            i1 = min(max(i1, 0), 255);
            i2 = min(max(i2, 0), 255);
            i3 = min(max(i3, 0), 255);
            atomicAdd(&cnt[i0 * 32 + lane], 1);
            atomicAdd(&cnt[i1 * 32 + lane], 1);
            atomicAdd(&cnt[i2 * 32 + lane], 1);
            atomicAdd(&cnt[i3 * 32 + lane], 1);
        }
    }
    __syncthreads();

    // Merge: thread t owns bin t; sum its 32 lane columns with a rotated
    // read order ((k+t)&31 -> distinct banks across lanes), 1 global atomic.
    int v = 0;
    #pragma unroll
    for (int k = 0; k < 32; k++)
        v += cnt[t * 32 + ((k + t) & 31)];
    atomicAdd(&g_hist[b][t], v);
}

// One block per batch: block b reads its 256-bin row (one coalesced 1KB
// burst), zeros it for the next replay, computes sum(p*log p), and
// accumulates partial/NB into out[0].
__global__ void __launch_bounds__(THREADS)
entropy_kernel(float* __restrict__ out) {
    __shared__ float warp_sum[THREADS / 32];
    const int b = blockIdx.x;
    const int t = threadIdx.x;

    const float inv = 1.0f / NUM_PIXEL;

    int raw = g_hist[b][t];
    g_hist[b][t] = 0;                      // cleanup for next replay
    // bin-0 quirk: reference overwrites bin0 count with H*W.
    float cnt = (t == 0) ? (float)HW : (float)raw;
    float p = (cnt + 1.0f) * inv;          // '+1' smoothing
    float acc = p * __logf(p);             // MUFU LG2 path; ~1e-6 rel err

    #pragma unroll
    for (int m = 16; m > 0; m >>= 1)
        acc += __shfl_xor_sync(0xFFFFFFFF, acc, m);
    if ((t & 31) == 0) warp_sum[t >> 5] = acc;
    __syncthreads();
    if (t < 32) {
        float v = (t < THREADS / 32) ? warp_sum[t] : 0.0f;
        #pragma unroll
        for (int m = 4; m > 0; m >>= 1)
            v += __shfl_xor_sync(0xFFFFFFFF, v, m);
        if (t == 0) atomicAdd(out, v * (1.0f / (float)NB));
    }
}

extern "C" void kernel_launch(void* const* d_in, const int* in_sizes, int n_in,
                              void* d_out, int out_size) {
    const float* x = (const float*)d_in[0];
    float* out = (float*)d_out;

    hist_kernel<<<dim3(BLK_PER_B, NB), THREADS>>>(x, out);
    entropy_kernel<<<NB, THREADS>>>(out);
}